// round 1
// baseline (speedup 1.0000x reference)
#include <cuda_runtime.h>
#include <math.h>

#define Nn   8192
#define Dd   128
#define BM   64
#define BN   256
#define NT   256
#define TEMP_INV 2.0f
#define EPSf 1e-8f

// Scratch: transposed embeddings ET[k][n] (4MB) + reduction cells.
__device__ float g_ET[Dd * Nn];
__device__ float g_loss_sum;
__device__ int   g_valid_count;
__device__ int   g_ccount[3];

__global__ void k_setup(const int* __restrict__ labels) {
    __shared__ int cnt[3];
    int t = threadIdx.x;
    if (t < 3) cnt[t] = 0;
    if (t == 0) { g_loss_sum = 0.f; g_valid_count = 0; }
    __syncthreads();
    for (int i = t; i < Nn; i += NT) atomicAdd(&cnt[labels[i] + 1], 1);
    __syncthreads();
    if (t < 3) g_ccount[t] = cnt[t];
}

__global__ void k_transpose(const float* __restrict__ E) {
    int o = blockIdx.x * blockDim.x + threadIdx.x;  // over Dd*Nn outputs
    int k = o >> 13;            // o / 8192
    int n = o & (Nn - 1);
    g_ET[o] = E[n * Dd + k];    // coalesced writes
}

__global__ __launch_bounds__(NT, 1)
void k_main(const int* __restrict__ labels) {
    extern __shared__ float smem[];
    float* As = smem;                     // [Dd][BM]   32KB
    float* Bs = smem + Dd * BM;           // [Dd][BN]  128KB
    int*   Ls = (int*)(smem + Dd * (BM + BN)); // [BN] labels

    const int tid  = threadIdx.x;
    const int trow = tid >> 5;            // warp id: owns rows {trow*4+i, 32+trow*4+i}
    const int tcol = tid & 31;
    const int r0f  = trow * 4;
    const int c0f  = tcol * 4;
    const int rowBase = blockIdx.x * BM;

    const float4* ET4 = (const float4*)g_ET;

    // ---- load A tile As[k][m], coalesced from ET, conflict-free STS ----
    #pragma unroll
    for (int p = 0; p < 8; p++) {
        int fidx = p * NT + tid;          // 0..2047 float4s
        int k  = fidx >> 4;               // 16 float4 per k-row
        int mq = fidx & 15;
        float4 v = ET4[k * (Nn / 4) + (rowBase >> 2) + mq];
        *(float4*)&As[k * BM + mq * 4] = v;
    }

    // per-thread per-row state (8 rows)
    int   li[8];
    float m[8], sp[8], st[8];
    #pragma unroll
    for (int rg = 0; rg < 2; rg++)
        #pragma unroll
        for (int i = 0; i < 4; i++) {
            int idx = rg * 4 + i;
            li[idx] = labels[rowBase + rg * 32 + r0f + i];
            m[idx] = -INFINITY; sp[idx] = 0.f; st[idx] = 0.f;
        }

    for (int jt = 0; jt < Nn / BN; jt++) {
        const int colBase = jt * BN;
        __syncthreads();                  // protect Bs/Ls from previous iter readers
        // ---- load B tile Bs[k][n] + labels ----
        #pragma unroll
        for (int p = 0; p < 32; p++) {
            int fidx = p * NT + tid;      // 0..8191 float4s
            int k  = fidx >> 6;           // 64 float4 per k-row
            int nq = fidx & 63;
            float4 v = ET4[k * (Nn / 4) + (colBase >> 2) + nq];
            *(float4*)&Bs[k * BN + nq * 4] = v;
        }
        Ls[tid] = labels[colBase + tid];
        __syncthreads();

        // ---- register-tiled 64x256x128 fp32 GEMM fragment (8x8/thread) ----
        float acc[2][4][2][4];
        #pragma unroll
        for (int a = 0; a < 2; a++)
            #pragma unroll
            for (int b = 0; b < 4; b++)
                #pragma unroll
                for (int c = 0; c < 2; c++)
                    #pragma unroll
                    for (int d = 0; d < 4; d++) acc[a][b][c][d] = 0.f;

        #pragma unroll 8
        for (int k = 0; k < Dd; k++) {
            float4 a0 = *(const float4*)&As[k * BM + r0f];        // broadcast
            float4 a1 = *(const float4*)&As[k * BM + 32 + r0f];
            float4 b0 = *(const float4*)&Bs[k * BN + c0f];        // conflict-free
            float4 b1 = *(const float4*)&Bs[k * BN + 128 + c0f];
            float av[2][4] = {{a0.x,a0.y,a0.z,a0.w},{a1.x,a1.y,a1.z,a1.w}};
            float bv[2][4] = {{b0.x,b0.y,b0.z,b0.w},{b1.x,b1.y,b1.z,b1.w}};
            #pragma unroll
            for (int rg = 0; rg < 2; rg++)
                #pragma unroll
                for (int i = 0; i < 4; i++)
                    #pragma unroll
                    for (int cg = 0; cg < 2; cg++)
                        #pragma unroll
                        for (int j = 0; j < 4; j++)
                            acc[rg][i][cg][j] = fmaf(av[rg][i], bv[cg][j], acc[rg][i][cg][j]);
        }

        // ---- fused online-softmax class-sum epilogue ----
        int lj[2][4];
        #pragma unroll
        for (int cg = 0; cg < 2; cg++)
            #pragma unroll
            for (int j = 0; j < 4; j++)
                lj[cg][j] = Ls[cg * 128 + c0f + j];

        #pragma unroll
        for (int rg = 0; rg < 2; rg++)
            #pragma unroll
            for (int i = 0; i < 4; i++) {
                int idx = rg * 4 + i;
                int growi = rowBase + rg * 32 + r0f + i;   // global row
                float cc[2][4];
                float tmax = -INFINITY;
                #pragma unroll
                for (int cg = 0; cg < 2; cg++)
                    #pragma unroll
                    for (int j = 0; j < 4; j++) {
                        cc[cg][j] = acc[rg][i][cg][j] * TEMP_INV;
                        tmax = fmaxf(tmax, cc[cg][j]);
                    }
                float mnew  = fmaxf(m[idx], tmax);
                float scale = expf(m[idx] - mnew);         // exp(0)=1 exact; exp(-inf)=0
                float vsp = sp[idx] * scale, vst = st[idx] * scale;
                bool  lz  = (li[idx] == 0);
                #pragma unroll
                for (int cg = 0; cg < 2; cg++)
                    #pragma unroll
                    for (int j = 0; j < 4; j++) {
                        float x = cc[cg][j] - mnew;
                        // expf underflows to exactly 0 below ~-87.3; guard skips MUFU work
                        float e = (x > -90.f) ? expf(x) : 0.f;
                        int coln = colBase + cg * 128 + c0f + j;
                        if (coln == growi) e = 0.f;        // diagonal excluded from sums
                        vst += e;
                        bool p = lz || (lj[cg][j] == li[idx]) || (lj[cg][j] == 0);
                        vsp += p ? e : 0.f;
                    }
                sp[idx] = vsp; st[idx] = vst; m[idx] = mnew;
            }
    }

    // ---- warp butterfly log-sum-exp merge (32 lanes share each row) ----
    #pragma unroll
    for (int off = 16; off > 0; off >>= 1) {
        #pragma unroll
        for (int idx = 0; idx < 8; idx++) {
            float mo  = __shfl_xor_sync(0xFFFFFFFFu, m[idx],  off);
            float spo = __shfl_xor_sync(0xFFFFFFFFu, sp[idx], off);
            float sto = __shfl_xor_sync(0xFFFFFFFFu, st[idx], off);
            float M  = fmaxf(m[idx], mo);
            float s1 = expf(m[idx] - M), s2 = expf(mo - M);
            sp[idx] = sp[idx] * s1 + spo * s2;
            st[idx] = st[idx] * s1 + sto * s2;
            m[idx]  = M;
        }
    }

    if (tcol == 0) {
        float lsum = 0.f; int lcnt = 0;
        #pragma unroll
        for (int idx = 0; idx < 8; idx++) {
            int  l = li[idx];
            bool valid = (l == 0) ? ((Nn - 1) > 0)
                                  : ((g_ccount[l + 1] + g_ccount[1] - 1) > 0);
            // pos+neg == st (both exclude diagonal)
            float loss = -logf((sp[idx] + EPSf) / (st[idx] + EPSf));
            if (valid) { lsum += loss; lcnt++; }
        }
        atomicAdd(&g_loss_sum, lsum);
        atomicAdd(&g_valid_count, lcnt);
    }
}

__global__ void k_final(float* __restrict__ out) {
    float s = g_loss_sum;
    int   c = g_valid_count;
    int   cm = c > 1 ? c : 1;
    out[0] = (c > 0) ? (s / (float)cm) : 0.f;
}

extern "C" void kernel_launch(void* const* d_in, const int* in_sizes, int n_in,
                              void* d_out, int out_size) {
    const int*   labels = (const int*)d_in[0];     // int32 in {-1,0,1}, [8192]
    const float* E      = (const float*)d_in[1];   // float32 [8192,128]
    (void)in_sizes; (void)n_in; (void)out_size;

    const int smem_bytes = (Dd * (BM + BN)) * (int)sizeof(float) + BN * (int)sizeof(int);
    cudaFuncSetAttribute(k_main, cudaFuncAttributeMaxDynamicSharedMemorySize, smem_bytes);

    k_setup<<<1, NT>>>(labels);
    k_transpose<<<(Nn * Dd) / NT, NT>>>(E);
    k_main<<<Nn / BM, NT, smem_bytes>>>(labels);
    k_final<<<1, 1>>>((float*)d_out);
}

// round 11
// speedup vs baseline: 5.8411x; 5.8411x over previous
#include <cuda_runtime.h>
#include <cuda_bf16.h>
#include <math.h>
#include <stdint.h>

#define Nn 8192
#define Dd 128
#define STRIPS 8            // blockIdx.y strips; each covers 1024 cols = 8 j-tiles
#define EPSf 1e-8f

// ---- device scratch (no allocations allowed) ----
__device__ uint4  g_Ebf4[Nn * 16];        // bf16(sqrt2*E), row-major, 256B/row, 2MB
__device__ float  g_diag[Nn];             // d_i = 2*||e_i||^2 (fp32)
__device__ float  g_pm [STRIPS * Nn];
__device__ float  g_psp[STRIPS * Nn];
__device__ float  g_pst[STRIPS * Nn];
__device__ float  g_loss_sum;
__device__ int    g_valid_count;
__device__ int    g_ccount[3];

// ---------------- prep: label counts + zero reductions ----------------
__global__ void k_setup(const int* __restrict__ labels) {
    __shared__ int cnt[3];
    int t = threadIdx.x;
    if (t < 3) cnt[t] = 0;
    if (t == 0) { g_loss_sum = 0.f; g_valid_count = 0; }
    __syncthreads();
    for (int i = t; i < Nn; i += 256) atomicAdd(&cnt[labels[i] + 1], 1);
    __syncthreads();
    if (t < 3) g_ccount[t] = cnt[t];
}

// ---------------- prep: bf16 convert (x sqrt2) + row diag norms ----------------
__global__ void k_prep(const float* __restrict__ E) {
    int w = threadIdx.x >> 5, lane = threadIdx.x & 31;
    int row = blockIdx.x * 8 + w;                  // 1024 blocks * 8 rows
    const float4* E4 = (const float4*)E;
    float4 v = E4[row * 32 + lane];
    float sq = v.x*v.x + v.y*v.y + v.z*v.z + v.w*v.w;
    #pragma unroll
    for (int o = 16; o; o >>= 1) sq += __shfl_xor_sync(0xFFFFFFFFu, sq, o);
    if (lane == 0) g_diag[row] = 2.f * sq;
    const float s = 1.41421356237f;                // fold 1/T=2 as sqrt2*sqrt2
    __nv_bfloat162* out = (__nv_bfloat162*)g_Ebf4;
    out[row * 64 + lane * 2]     = __floats2bfloat162_rn(v.x * s, v.y * s);
    out[row * 64 + lane * 2 + 1] = __floats2bfloat162_rn(v.z * s, v.w * s);
}

// ---------------- mma helpers ----------------
__device__ __forceinline__ void ldsm4(uint32_t* r, uint32_t addr) {
    asm volatile("ldmatrix.sync.aligned.m8n8.x4.shared.b16 {%0,%1,%2,%3}, [%4];"
        : "=r"(r[0]), "=r"(r[1]), "=r"(r[2]), "=r"(r[3]) : "r"(addr));
}
__device__ __forceinline__ void mma16816(float* c, const uint32_t* a, uint32_t b0, uint32_t b1) {
    asm volatile("mma.sync.aligned.m16n8k16.row.col.f32.bf16.bf16.f32 "
        "{%0,%1,%2,%3}, {%4,%5,%6,%7}, {%8,%9}, {%0,%1,%2,%3};"
        : "+f"(c[0]), "+f"(c[1]), "+f"(c[2]), "+f"(c[3])
        : "r"(a[0]), "r"(a[1]), "r"(a[2]), "r"(a[3]), "r"(b0), "r"(b1));
}

// ---------------- main: 128x128 tiles, bf16 HMMA, online-softmax epilogue ----------------
__global__ __launch_bounds__(256, 1)
void k_main(const int* __restrict__ labels) {
    extern __shared__ char smem[];
    uint4* As4 = (uint4*)smem;                 // [128 rows][16 chunks] swizzled
    uint4* Bs4 = (uint4*)(smem + 32768);
    int*   Ls  = (int*)  (smem + 65536);

    const int tid  = threadIdx.x;
    const int w    = tid >> 5;
    const int lane = tid & 31;
    const int rowBase = blockIdx.x * 128;

    const uint32_t sA = (uint32_t)__cvta_generic_to_shared(As4);
    const uint32_t sB = (uint32_t)__cvta_generic_to_shared(Bs4);

    // ldmatrix per-thread invariants (canonical sm_80 fragment mappings)
    const int arow  = w * 16 + (lane & 7) + (((lane >> 3) & 1) << 3); // A smem row
    const int aKc   = lane >> 4;                                       // A k-chunk sel
    const int bjoff = (((lane >> 4) & 1) << 3) + (lane & 7);           // B row offset in 16-col group
    const int bKc   = (lane >> 3) & 1;

    // ---- load A tile (swizzled), resident for all j-tiles ----
    #pragma unroll
    for (int it = 0; it < 8; it++) {
        int ci = it * 256 + tid;        // 2048 chunks
        int r = ci >> 4, c = ci & 15;
        As4[r * 16 + (c ^ (r & 7))] = g_Ebf4[(rowBase + r) * 16 + c];
    }

    // ---- per-thread row state (2 rows), m initialized to exact diag value ----
    const int grow0 = rowBase + w * 16 + (lane >> 2);   // row for c0,c1
    const int grow1 = grow0 + 8;                        // row for c2,c3
    int   li0 = labels[grow0],  li1 = labels[grow1];
    float m0 = g_diag[grow0],   m1 = g_diag[grow1];
    float sp0 = 0.f, st0 = 0.f, sp1 = 0.f, st1 = 0.f;

    for (int jt = 0; jt < 8; jt++) {
        const int colBase = blockIdx.y * 1024 + jt * 128;
        __syncthreads();
        #pragma unroll
        for (int it = 0; it < 8; it++) {
            int ci = it * 256 + tid;
            int r = ci >> 4, c = ci & 15;
            Bs4[r * 16 + (c ^ (r & 7))] = g_Ebf4[(colBase + r) * 16 + c];
        }
        if (tid < 128) Ls[tid] = labels[colBase + tid];
        __syncthreads();

        float acc[16][4];
        #pragma unroll
        for (int nt = 0; nt < 16; nt++)
            #pragma unroll
            for (int d = 0; d < 4; d++) acc[nt][d] = 0.f;

        #pragma unroll
        for (int ks = 0; ks < 8; ks++) {
            uint32_t a[4];
            ldsm4(a, sA + arow * 256 + (((ks * 2 + aKc) ^ (arow & 7)) << 4));
            uint32_t b[8][4];
            #pragma unroll
            for (int q = 0; q < 8; q++) {
                int j = q * 16 + bjoff;
                ldsm4(b[q], sB + j * 256 + (((ks * 2 + bKc) ^ (j & 7)) << 4));
            }
            #pragma unroll
            for (int q = 0; q < 8; q++) {
                mma16816(acc[2 * q],     a, b[q][0], b[q][1]);
                mma16816(acc[2 * q + 1], a, b[q][2], b[q][3]);
            }
        }

        // ---- epilogue: per-row tile max; skip exactly when all exps underflow ----
        float t0 = -1e30f, t1 = -1e30f;
        #pragma unroll
        for (int nt = 0; nt < 16; nt++) {
            t0 = fmaxf(t0, fmaxf(acc[nt][0], acc[nt][1]));
            t1 = fmaxf(t1, fmaxf(acc[nt][2], acc[nt][3]));
        }
        const int cb = colBase + (lane & 3) * 2;
        const bool lz0 = (li0 == 0), lz1 = (li1 == 0);

        if (t0 >= m0 - 90.f) {          // rare path
            float mnew = fmaxf(m0, t0);
            float sc = expf(m0 - mnew); sp0 *= sc; st0 *= sc;
            #pragma unroll
            for (int nt = 0; nt < 16; nt++)
                #pragma unroll
                for (int d = 0; d < 2; d++) {
                    float x = acc[nt][d] - mnew;
                    float e = (x > -90.f) ? expf(x) : 0.f;
                    int coln = cb + nt * 8 + d;
                    if (coln == grow0) e = 0.f;          // exclude diagonal from sums
                    st0 += e;
                    int lj = Ls[nt * 8 + (lane & 3) * 2 + d];
                    bool p = lz0 || (lj == li0) || (lj == 0);
                    sp0 += p ? e : 0.f;
                }
            m0 = mnew;
        }
        if (t1 >= m1 - 90.f) {
            float mnew = fmaxf(m1, t1);
            float sc = expf(m1 - mnew); sp1 *= sc; st1 *= sc;
            #pragma unroll
            for (int nt = 0; nt < 16; nt++)
                #pragma unroll
                for (int d = 0; d < 2; d++) {
                    float x = acc[nt][2 + d] - mnew;
                    float e = (x > -90.f) ? expf(x) : 0.f;
                    int coln = cb + nt * 8 + d;
                    if (coln == grow1) e = 0.f;
                    st1 += e;
                    int lj = Ls[nt * 8 + (lane & 3) * 2 + d];
                    bool p = lz1 || (lj == li1) || (lj == 0);
                    sp1 += p ? e : 0.f;
                }
            m1 = mnew;
        }
    }

    // ---- merge across the 4 lanes sharing each row (lane groups of 4) ----
    #pragma unroll
    for (int off = 1; off <= 2; off <<= 1) {
        float mo, spo, sto, M, e1, e2;
        mo  = __shfl_xor_sync(0xFFFFFFFFu, m0,  off);
        spo = __shfl_xor_sync(0xFFFFFFFFu, sp0, off);
        sto = __shfl_xor_sync(0xFFFFFFFFu, st0, off);
        M = fmaxf(m0, mo); e1 = expf(m0 - M); e2 = expf(mo - M);
        sp0 = sp0 * e1 + spo * e2; st0 = st0 * e1 + sto * e2; m0 = M;

        mo  = __shfl_xor_sync(0xFFFFFFFFu, m1,  off);
        spo = __shfl_xor_sync(0xFFFFFFFFu, sp1, off);
        sto = __shfl_xor_sync(0xFFFFFFFFu, st1, off);
        M = fmaxf(m1, mo); e1 = expf(m1 - M); e2 = expf(mo - M);
        sp1 = sp1 * e1 + spo * e2; st1 = st1 * e1 + sto * e2; m1 = M;
    }
    if ((lane & 3) == 0) {
        int p0 = blockIdx.y * Nn + grow0;
        int p1 = blockIdx.y * Nn + grow1;
        g_pm[p0] = m0; g_psp[p0] = sp0; g_pst[p0] = st0;
        g_pm[p1] = m1; g_psp[p1] = sp1; g_pst[p1] = st1;
    }
}

// ---------------- merge strips + loss reduction ----------------
__global__ void k_merge(const int* __restrict__ labels) {
    int row = blockIdx.x * 256 + threadIdx.x;
    float M = g_pm[row];
    #pragma unroll
    for (int s = 1; s < STRIPS; s++) M = fmaxf(M, g_pm[s * Nn + row]);
    float sp = 0.f, st = 0.f;
    #pragma unroll
    for (int s = 0; s < STRIPS; s++) {
        float sc = expf(g_pm[s * Nn + row] - M);
        sp += g_psp[s * Nn + row] * sc;
        st += g_pst[s * Nn + row] * sc;
    }
    int l = labels[row];
    bool valid = (l == 0) ? true : ((g_ccount[l + 1] + g_ccount[1] - 1) > 0);
    float loss = -logf((sp + EPSf) / (st + EPSf));
    float lv = valid ? loss : 0.f;
    int   cv = valid ? 1 : 0;
    #pragma unroll
    for (int o = 16; o; o >>= 1) {
        lv += __shfl_xor_sync(0xFFFFFFFFu, lv, o);
        cv += __shfl_xor_sync(0xFFFFFFFFu, cv, o);
    }
    if ((threadIdx.x & 31) == 0) {
        atomicAdd(&g_loss_sum, lv);
        atomicAdd(&g_valid_count, cv);
    }
}

__global__ void k_final(float* __restrict__ out) {
    float s = g_loss_sum;
    int   c = g_valid_count;
    int   cm = c > 1 ? c : 1;
    out[0] = (c > 0) ? (s / (float)cm) : 0.f;
}

extern "C" void kernel_launch(void* const* d_in, const int* in_sizes, int n_in,
                              void* d_out, int out_size) {
    const int*   labels = (const int*)d_in[0];     // int32 in {-1,0,1}, [8192]
    const float* E      = (const float*)d_in[1];   // float32 [8192,128]
    (void)in_sizes; (void)n_in; (void)out_size;

    const int smem_bytes = 65536 + 128 * (int)sizeof(int);
    cudaFuncSetAttribute(k_main, cudaFuncAttributeMaxDynamicSharedMemorySize, smem_bytes);

    k_setup<<<1, 256>>>(labels);
    k_prep <<<Nn / 8, 256>>>(E);
    k_main <<<dim3(Nn / 128, STRIPS), 256, smem_bytes>>>(labels);
    k_merge<<<Nn / 256, 256>>>(labels);
    k_final<<<1, 1>>>((float*)d_out);
}